// round 13
// baseline (speedup 1.0000x reference)
#include <cuda_runtime.h>
#include <cuda_fp16.h>
#include <math.h>

#define NN 100000
#define EE 1600000
#define NSCAN 196            // ceil(NN/512)

// ---------------- scratch (device globals; no allocation) ----------------
__device__ __half  d_g1h[NN * 64];   // (x@W1)*dinv  fp16  [N,64]  128B rows
__device__ float4  d_h[NN * 16];     // relu output  fp32  [N,64]
__device__ __half  d_g2h[NN * 64];   // (h@W2)*dinv  fp16  [N,40] padded to 64
__device__ float   d_dinv[NN];
__device__ int     d_degc[NN];       // zeroed by k_agg2 of the PREVIOUS run
__device__ int     d_start[NN];
__device__ int     d_cursor[NN];
__device__ int     d_adj[EE];
__device__ int     d_gbase;

// ---------------- f32x2 helpers ------------------------------------------
#define PACK2(dst, a, b) \
    asm("mov.b64 %0, {%1,%2};" : "=l"(dst) : "r"(__float_as_uint(a)), "r"(__float_as_uint(b)))
#define FMA2(acc, a, b) \
    asm("fma.rn.f32x2 %0, %1, %2, %0;" : "+l"(acc) : "l"(a), "l"(b))
#define UNPACK2(lo, hi, src) do { unsigned _u0, _u1; \
    asm("mov.b64 {%0,%1}, %2;" : "=r"(_u0), "=r"(_u1) : "l"(src)); \
    lo = __uint_as_float(_u0); hi = __uint_as_float(_u1); } while (0)

// ---------------- degree over targets (col); resets gbase ----------------
__global__ void k_count(const int* __restrict__ col) {
    int i = blockIdx.x * blockDim.x + threadIdx.x;
    if (i == 0) d_gbase = 0;           // consumed by k_scan (next kernel)
    if (i < EE) atomicAdd(&d_degc[__ldg(col + i)], 1);
}

// ---------------- single-kernel scan: block scan + atomic base -----------
__global__ __launch_bounds__(512) void k_scan() {
    __shared__ int sh[512];
    __shared__ int base;
    int t = threadIdx.x;
    int i = blockIdx.x * 512 + t;
    int v = (i < NN) ? d_degc[i] : 0;
    sh[t] = v;
    __syncthreads();
#pragma unroll
    for (int off = 1; off < 512; off <<= 1) {
        int a = (t >= off) ? sh[t - off] : 0;
        __syncthreads();
        sh[t] += a;
        __syncthreads();
    }
    if (t == 511) base = atomicAdd(&d_gbase, sh[511]);
    __syncthreads();
    if (i < NN) {
        int s = base + sh[t] - v;
        d_start[i] = s;
        d_cursor[i] = s;
        d_dinv[i] = rsqrtf((float)(v + 1));   // +1 self loop
    }
}

// ---------------- CSR fill (standalone: low regs, full occupancy) --------
__global__ __launch_bounds__(256) void k_fill(const int* __restrict__ row,
                                              const int* __restrict__ col) {
    int e = blockIdx.x * blockDim.x + threadIdx.x;
    if (e >= EE) return;
    int c = __ldg(col + e);
    int p = atomicAdd(&d_cursor[c], 1);
    d_adj[p] = __ldg(row + e);
}

// ---------------- GEMM1: g1 = (x @ W1) * dinv -> fp16, f32x2 math --------
__global__ __launch_bounds__(256) void k_gemm1(const float4* __restrict__ x,
                                               const float* __restrict__ W) {
    __shared__ float ws[64 * 64];
    __shared__ float xs[64 * 68];
    int t = threadIdx.x;
    const float4* W4 = (const float4*)W;
#pragma unroll
    for (int i = 0; i < 4; i++) ((float4*)ws)[t + 256 * i] = __ldg(W4 + t + 256 * i);
    int node0 = blockIdx.x * 64;
#pragma unroll
    for (int i = 0; i < 4; i++) {
        int idx = t + 256 * i;
        int r = idx >> 4, c = idx & 15;
        int gr = node0 + r;
        float4 v = make_float4(0.f, 0.f, 0.f, 0.f);
        if (gr < NN) v = __ldg(x + gr * 16 + c);
        float* p = &xs[r * 68 + c * 4];
        p[0] = v.x; p[1] = v.y; p[2] = v.z; p[3] = v.w;
    }
    __syncthreads();
    int tx = t & 15, ty = t >> 4;
    unsigned long long acc[4][2];
#pragma unroll
    for (int i = 0; i < 4; i++) { acc[i][0] = 0ULL; acc[i][1] = 0ULL; }
#pragma unroll
    for (int k = 0; k < 64; k++) {
        float4 w = *(const float4*)&ws[k * 64 + tx * 4];
        unsigned long long wlo, whi;
        PACK2(wlo, w.x, w.y);
        PACK2(whi, w.z, w.w);
#pragma unroll
        for (int i = 0; i < 4; i++) {
            float xv = xs[(ty * 4 + i) * 68 + k];
            unsigned long long xv2;
            PACK2(xv2, xv, xv);
            FMA2(acc[i][0], wlo, xv2);
            FMA2(acc[i][1], whi, xv2);
        }
    }
#pragma unroll
    for (int i = 0; i < 4; i++) {
        int gr = node0 + ty * 4 + i;
        if (gr < NN) {
            float dv = d_dinv[gr];
            float a0, a1, a2, a3;
            UNPACK2(a0, a1, acc[i][0]);
            UNPACK2(a2, a3, acc[i][1]);
            __half2 ha = __float22half2_rn(make_float2(a0 * dv, a1 * dv));
            __half2 hb = __float22half2_rn(make_float2(a2 * dv, a3 * dv));
            ((__half2*)d_g1h)[gr * 32 + tx * 2] = ha;
            ((__half2*)d_g1h)[gr * 32 + tx * 2 + 1] = hb;
        }
    }
}

// ---------------- agg1 (fp16 gather) + relu/bias: one warp per node ------
// 4 edge groups x 8 lanes; each lane owns 8 features (uint4 = 8 halves).
__global__ __launch_bounds__(256) void k_agg1(const float* __restrict__ b1) {
    int w = (blockIdx.x * blockDim.x + threadIdx.x) >> 5;
    if (w >= NN) return;
    int lane = threadIdx.x & 31;
    int grp = lane >> 3, fl = lane & 7;
    int s = d_start[w], d = d_degc[w];
    const uint4* G = (const uint4*)d_g1h;
    float acc[8];
#pragma unroll
    for (int j = 0; j < 8; j++) acc[j] = 0.f;
#pragma unroll 4
    for (int i = grp; i < d; i += 4) {
        int r = __ldg(d_adj + s + i);
        uint4 u = __ldg(G + r * 8 + fl);
        const __half2* hp = (const __half2*)&u;
        float2 f;
        f = __half22float2(hp[0]); acc[0] += f.x; acc[1] += f.y;
        f = __half22float2(hp[1]); acc[2] += f.x; acc[3] += f.y;
        f = __half22float2(hp[2]); acc[4] += f.x; acc[5] += f.y;
        f = __half22float2(hp[3]); acc[6] += f.x; acc[7] += f.y;
    }
#pragma unroll
    for (int j = 0; j < 8; j++) {
        acc[j] += __shfl_xor_sync(0xFFFFFFFFu, acc[j], 8);
        acc[j] += __shfl_xor_sync(0xFFFFFFFFu, acc[j], 16);
    }
    if (grp == 0) {
        float dv = d_dinv[w];
        uint4 us = __ldg(G + w * 8 + fl);          // self message
        const __half2* hs = (const __half2*)&us;
        float gs[8];
        float2 f;
        f = __half22float2(hs[0]); gs[0] = f.x; gs[1] = f.y;
        f = __half22float2(hs[1]); gs[2] = f.x; gs[3] = f.y;
        f = __half22float2(hs[2]); gs[4] = f.x; gs[5] = f.y;
        f = __half22float2(hs[3]); gs[6] = f.x; gs[7] = f.y;
        float4 ba = __ldg((const float4*)b1 + fl * 2);
        float4 bb = __ldg((const float4*)b1 + fl * 2 + 1);
        float4 h0, h1;
        h0.x = fmaxf(dv * (acc[0] + gs[0]) + ba.x, 0.f);
        h0.y = fmaxf(dv * (acc[1] + gs[1]) + ba.y, 0.f);
        h0.z = fmaxf(dv * (acc[2] + gs[2]) + ba.z, 0.f);
        h0.w = fmaxf(dv * (acc[3] + gs[3]) + ba.w, 0.f);
        h1.x = fmaxf(dv * (acc[4] + gs[4]) + bb.x, 0.f);
        h1.y = fmaxf(dv * (acc[5] + gs[5]) + bb.y, 0.f);
        h1.z = fmaxf(dv * (acc[6] + gs[6]) + bb.z, 0.f);
        h1.w = fmaxf(dv * (acc[7] + gs[7]) + bb.w, 0.f);
        d_h[w * 16 + fl * 2] = h0;
        d_h[w * 16 + fl * 2 + 1] = h1;
    }
}

// ---------------- GEMM2: g2 = (h @ W2) * dinv -> fp16, f32x2 math --------
__global__ __launch_bounds__(320) void k_gemm2(const float* __restrict__ W2) {
    __shared__ float ws[64 * 40];
    __shared__ float xs[128 * 68];
    int t = threadIdx.x;
    for (int i = t; i < 640; i += 320)
        ((float4*)ws)[i] = __ldg((const float4*)W2 + i);
    int node0 = blockIdx.x * 128;
    for (int idx = t; idx < 2048; idx += 320) {
        int r = idx >> 4, c = idx & 15;
        int gr = node0 + r;
        float4 v = make_float4(0.f, 0.f, 0.f, 0.f);
        if (gr < NN) v = d_h[gr * 16 + c];
        float* p = &xs[r * 68 + c * 4];
        p[0] = v.x; p[1] = v.y; p[2] = v.z; p[3] = v.w;
    }
    __syncthreads();
    int tx = t % 10, ty = t / 10;
    unsigned long long acc[4][2];
#pragma unroll
    for (int i = 0; i < 4; i++) { acc[i][0] = 0ULL; acc[i][1] = 0ULL; }
#pragma unroll
    for (int k = 0; k < 64; k++) {
        float4 w = *(const float4*)&ws[k * 40 + tx * 4];
        unsigned long long wlo, whi;
        PACK2(wlo, w.x, w.y);
        PACK2(whi, w.z, w.w);
#pragma unroll
        for (int i = 0; i < 4; i++) {
            float xv = xs[(ty * 4 + i) * 68 + k];
            unsigned long long xv2;
            PACK2(xv2, xv, xv);
            FMA2(acc[i][0], wlo, xv2);
            FMA2(acc[i][1], whi, xv2);
        }
    }
#pragma unroll
    for (int i = 0; i < 4; i++) {
        int gr = node0 + ty * 4 + i;
        if (gr < NN) {
            float dv = d_dinv[gr];
            float a0, a1, a2, a3;
            UNPACK2(a0, a1, acc[i][0]);
            UNPACK2(a2, a3, acc[i][1]);
            __half2 ha = __float22half2_rn(make_float2(a0 * dv, a1 * dv));
            __half2 hb = __float22half2_rn(make_float2(a2 * dv, a3 * dv));
            ((__half2*)d_g2h)[gr * 32 + tx * 2] = ha;
            ((__half2*)d_g2h)[gr * 32 + tx * 2 + 1] = hb;
        }
    }
}

// ---------------- agg2 (fp16 gather) + bias + log_softmax + cleanup ------
// 3 edge groups x 10 lanes; each lane owns 4 features (uint2 = 4 halves).
__global__ __launch_bounds__(256) void k_agg2(const float* __restrict__ b2,
                                              float* __restrict__ out) {
    int w = (blockIdx.x * blockDim.x + threadIdx.x) >> 5;
    if (w >= NN) return;
    int lane = threadIdx.x & 31;
    int grp = lane / 10, fl = lane % 10;
    int s = d_start[w], d = d_degc[w];
    if (lane == 0) d_degc[w] = 0;      // cleanup for the next graph replay
    const uint2* G = (const uint2*)d_g2h;      // 16 uint2 per padded row
    float a0 = 0.f, a1 = 0.f, a2 = 0.f, a3 = 0.f;
    if (grp < 3) {
#pragma unroll 4
        for (int i = grp; i < d; i += 3) {
            int r = __ldg(d_adj + s + i);
            uint2 u = __ldg(G + r * 16 + fl);
            const __half2* hp = (const __half2*)&u;
            float2 f0 = __half22float2(hp[0]), f1 = __half22float2(hp[1]);
            a0 += f0.x; a1 += f0.y; a2 += f1.x; a3 += f1.y;
        }
    }
    // combine the 3 edge groups: lane l (<10) sums lanes l, l+10, l+20
    a0 += __shfl_sync(0xFFFFFFFFu, a0, lane + 10) + __shfl_sync(0xFFFFFFFFu, a0, lane + 20);
    a1 += __shfl_sync(0xFFFFFFFFu, a1, lane + 10) + __shfl_sync(0xFFFFFFFFu, a1, lane + 20);
    a2 += __shfl_sync(0xFFFFFFFFu, a2, lane + 10) + __shfl_sync(0xFFFFFFFFu, a2, lane + 20);
    a3 += __shfl_sync(0xFFFFFFFFu, a3, lane + 10) + __shfl_sync(0xFFFFFFFFu, a3, lane + 20);

    float4 z = make_float4(-INFINITY, -INFINITY, -INFINITY, -INFINITY);
    if (lane < 10) {
        float dv = d_dinv[w];
        uint2 us = __ldg(G + w * 16 + lane);       // self message
        const __half2* hs = (const __half2*)&us;
        float2 g0 = __half22float2(hs[0]), g1 = __half22float2(hs[1]);
        float4 bb = __ldg((const float4*)b2 + lane);
        z.x = dv * (a0 + g0.x) + bb.x;
        z.y = dv * (a1 + g0.y) + bb.y;
        z.z = dv * (a2 + g1.x) + bb.z;
        z.w = dv * (a3 + g1.y) + bb.w;
    }
    float m = fmaxf(fmaxf(z.x, z.y), fmaxf(z.z, z.w));
#pragma unroll
    for (int o = 8; o; o >>= 1) m = fmaxf(m, __shfl_xor_sync(0xFFFFFFFFu, m, o));
    float sm = 0.f;
    if (lane < 10)
        sm = expf(z.x - m) + expf(z.y - m) + expf(z.z - m) + expf(z.w - m);
#pragma unroll
    for (int o = 8; o; o >>= 1) sm += __shfl_xor_sync(0xFFFFFFFFu, sm, o);
    if (lane < 10) {
        float lse = m + logf(sm);
        ((float4*)out)[w * 10 + lane] =
            make_float4(z.x - lse, z.y - lse, z.z - lse, z.w - lse);
    }
}

// ---------------- launch --------------------------------------------------
extern "C" void kernel_launch(void* const* d_in, const int* in_sizes, int n_in,
                              void* d_out, int out_size) {
    const float* x  = (const float*)d_in[0];
    const int*   ei = (const int*)d_in[1];
    const float* W1 = (const float*)d_in[2];
    const float* b1 = (const float*)d_in[3];
    const float* W2 = (const float*)d_in[4];
    const float* b2 = (const float*)d_in[5];
    const int* row = ei;        // edge_index[0] = sources (gathered)
    const int* col = ei + EE;   // edge_index[1] = targets (aggregated)
    float* out = (float*)d_out;

    k_count<<<(EE + 255) / 256, 256>>>(col);
    k_scan<<<NSCAN, 512>>>();
    k_fill<<<(EE + 255) / 256, 256>>>(row, col);
    k_gemm1<<<(NN + 63) / 64, 256>>>((const float4*)x, W1);
    k_agg1<<<(NN * 32 + 255) / 256, 256>>>(b1);
    k_gemm2<<<(NN + 127) / 128, 320>>>(W2);
    k_agg2<<<(NN * 32 + 255) / 256, 256>>>(b2, out);
}